// round 6
// baseline (speedup 1.0000x reference)
#include <cuda_runtime.h>

#define Bq   16
#define Kq   32
#define Lq   1024
#define Dq   128
#define NEWL 48

// ---- scratch ----
__device__ int   g_order[Bq * Lq];          // l indices sorted by segment, per batch
__device__ int   g_off[Bq * (NEWL + 1)];
__device__ float g_tsum[Bq * NEWL];

#define NEG_INF __int_as_float(0xff800000)
#define FMAX4(a, v) { a.x = fmaxf(a.x, v.x); a.y = fmaxf(a.y, v.y); \
                      a.z = fmaxf(a.z, v.z); a.w = fmaxf(a.w, v.w); }

// K1: heterogeneous blocks. Blocks [0,16): per-batch counting sort (prep).
// Blocks [16, 16+6144): almat one-hot float4 writes. prep latency hides under almat.
__global__ void __launch_bounds__(Lq) fused_kernel(const float* __restrict__ et,
                                                   float* __restrict__ out_a) {
    const int t = threadIdx.x;

    if (blockIdx.x < Bq) {
        // ---- prep: counting sort of l by segment, batch b ----
        const int b = blockIdx.x;
        __shared__ int   cnt[NEWL + 1];
        __shared__ int   off[NEWL + 1];
        __shared__ int   cur[NEWL + 1];
        __shared__ float ts[NEWL];

        if (t <= NEWL) { cnt[t] = 0; cur[t] = 0; }
        if (t < NEWL)  ts[t] = 0.f;
        __syncthreads();

        float tv = et[b * Lq + t];
        int   s  = (tv >= 0.f && tv < 48.f) ? (int)tv : NEWL;
        atomicAdd(&cnt[s], 1);
        if (s < NEWL) atomicAdd(&ts[s], tv);
        __syncthreads();

        if (t <= NEWL) {                       // parallel exclusive prefix
            int a = 0;
            for (int i = 0; i < t; ++i) a += cnt[i];
            off[t] = a;
        }
        __syncthreads();

        int pos = off[s] + atomicAdd(&cur[s], 1);
        g_order[b * Lq + pos] = t;

        if (t < NEWL)  g_tsum[b * NEWL + t] = ts[t];
        if (t <= NEWL) g_off[b * (NEWL + 1) + t] = off[t];
    } else {
        // ---- almat: (B,K,L,48) one-hot, float4 stores, 32-bit indexing ----
        unsigned g   = (blockIdx.x - Bq) * 1024u + t;   // float4 index, exact cover
        unsigned row = g / 12u;              // (b,k,l) flat
        unsigned q   = g - row * 12u;
        unsigned l   = row & (Lq - 1);
        unsigned b   = row >> 15;            // / (K*L), K*L = 2^15
        float tv = __ldg(&et[b * Lq + l]);
        int s = (tv >= 0.f && tv < 48.f) ? (int)tv : NEWL;
        float4 v = make_float4(0.f, 0.f, 0.f, 0.f);
        int o = s - (int)(q * 4u);
        if (o >= 0 && o < 4) (&v.x)[o] = 1.f;
        reinterpret_cast<float4*>(out_a)[g] = v;
    }
}

// K2: segmax + pad_mask + event_time. grid = (6, B*K), block = 256 (8 warps).
// Warp w owns segment s = bx*8 + w for column bk: reads its sorted index run
// from g_order (lane-uniform broadcast loads), gathers float4 rows with 4
// independent accumulators, writes its 512B output row. No smem, no block sync.
__global__ void __launch_bounds__(256) segmax_kernel(const float* __restrict__ h0,
                                                     const float* __restrict__ npm,
                                                     float* __restrict__ o_h,
                                                     float* __restrict__ o_pm,
                                                     float* __restrict__ o_et) {
    const int bk = blockIdx.y;            // 0..511
    const int b  = bk >> 5;               // K = 32
    const int w  = threadIdx.x >> 5;      // warp 0..7
    const int j  = threadIdx.x & 31;      // lane
    const int s  = blockIdx.x * 8 + w;    // this warp's segment

    const int off = __ldg(&g_off[b * (NEWL + 1) + s]);
    const int cnt = __ldg(&g_off[b * (NEWL + 1) + s + 1]) - off;
    const int* idx = g_order + b * Lq + off;

    const float4* base4 = reinterpret_cast<const float4*>(h0 + (size_t)bk * Lq * Dq) + j;
    float4 a0 = make_float4(NEG_INF, NEG_INF, NEG_INF, NEG_INF);
    float4 a1 = a0, a2 = a0, a3 = a0;
    int i = 0;
    for (; i + 4 <= cnt; i += 4) {
        int l0 = __ldg(&idx[i]);     int l1 = __ldg(&idx[i + 1]);
        int l2 = __ldg(&idx[i + 2]); int l3 = __ldg(&idx[i + 3]);
        float4 v0 = base4[l0 * 32];
        float4 v1 = base4[l1 * 32];
        float4 v2 = base4[l2 * 32];
        float4 v3 = base4[l3 * 32];
        FMAX4(a0, v0); FMAX4(a1, v1); FMAX4(a2, v2); FMAX4(a3, v3);
    }
    for (; i < cnt; ++i) {
        float4 v = base4[__ldg(&idx[i]) * 32];
        FMAX4(a0, v);
    }
    FMAX4(a0, a1); FMAX4(a2, a3); FMAX4(a0, a2);
    if (cnt < Lq) {                        // include_zero (empty segs: -inf -> 0)
        float4 z = make_float4(0.f, 0.f, 0.f, 0.f);
        FMAX4(a0, z);
    }
    reinterpret_cast<float4*>(o_h)[((size_t)bk * NEWL + s) * 32 + j] = a0;

    // msum (exact: 0/1 values), lane-strided gather + shuffle reduce
    const float* mrow = npm + (size_t)bk * Lq;
    float msum = 0.f;
    for (int i2 = j; i2 < cnt; i2 += 32) msum += mrow[__ldg(&idx[i2])];
    #pragma unroll
    for (int d = 16; d > 0; d >>= 1) msum += __shfl_down_sync(0xffffffffu, msum, d);
    if (j == 0) {
        float denom = fmaxf((float)cnt, 1.f);
        o_pm[bk * NEWL + s] = msum / denom;
        o_et[bk * NEWL + s] = __ldg(&g_tsum[b * NEWL + s]) / denom;
    }
}

extern "C" void kernel_launch(void* const* d_in, const int* in_sizes, int n_in,
                              void* d_out, int out_size) {
    const float* h0  = (const float*)d_in[0];
    const float* et  = (const float*)d_in[1];
    const float* npm = (const float*)d_in[2];
    float* out = (float*)d_out;

    float* o_h  = out;                              // (16,32,48,128) = 3,145,728
    float* o_et = out + 3145728;                    // (16,32,48)     =    24,576
    float* o_pm = out + 3145728 + 24576;            // (16,32,48)     =    24,576
    float* o_a  = out + 3145728 + 24576 + 24576;    // (16,32,1024,48)= 25,165,824

    fused_kernel<<<Bq + 6144, Lq>>>(et, o_a);       // prep blocks + almat blocks
    dim3 grid(6, Bq * Kq);
    segmax_kernel<<<grid, 256>>>(h0, npm, o_h, o_pm, o_et);
}

// round 7
// speedup vs baseline: 1.0514x; 1.0514x over previous
#include <cuda_runtime.h>

#define Bq   16
#define Kq   32
#define Lq   1024
#define Dq   128
#define NEWL 48

// ---- scratch ----
__device__ int   g_order[Bq * Lq];          // l indices sorted by segment, per batch
__device__ int   g_off[Bq * (NEWL + 1)];
__device__ float g_tsum[Bq * NEWL];

#define NEG_INF __int_as_float(0xff800000)
#define FMAX4(a, v) { a.x = fmaxf(a.x, v.x); a.y = fmaxf(a.y, v.y); \
                      a.z = fmaxf(a.z, v.z); a.w = fmaxf(a.w, v.w); }

// K1: heterogeneous 256-thread blocks. Blocks [0,16): per-batch counting sort
// (4 elems/thread). Blocks [16, 16+24576): almat float4 writes (exact cover).
__global__ void __launch_bounds__(256) fused_kernel(const float* __restrict__ et,
                                                    float* __restrict__ out_a) {
    const int t = threadIdx.x;

    if (blockIdx.x < Bq) {
        // ---- prep: counting sort of l by segment, batch b ----
        const int b = blockIdx.x;
        __shared__ int   cnt[NEWL + 1];
        __shared__ int   off[NEWL + 1];
        __shared__ int   cur[NEWL + 1];
        __shared__ float ts[NEWL];

        if (t <= NEWL) { cnt[t] = 0; cur[t] = 0; }
        if (t < NEWL)  ts[t] = 0.f;
        __syncthreads();

        int   ls[4], ss[4];
        #pragma unroll
        for (int r = 0; r < 4; ++r) {
            int   l  = r * 256 + t;                 // coalesced
            float tv = et[b * Lq + l];
            int   s  = (tv >= 0.f && tv < 48.f) ? (int)tv : NEWL;
            ls[r] = l; ss[r] = s;
            atomicAdd(&cnt[s], 1);
            if (s < NEWL) atomicAdd(&ts[s], tv);
        }
        __syncthreads();

        if (t <= NEWL) {                            // parallel exclusive prefix
            int a = 0;
            for (int i = 0; i < t; ++i) a += cnt[i];
            off[t] = a;
        }
        __syncthreads();

        #pragma unroll
        for (int r = 0; r < 4; ++r) {
            int pos = off[ss[r]] + atomicAdd(&cur[ss[r]], 1);
            g_order[b * Lq + pos] = ls[r];
        }
        if (t < NEWL)  g_tsum[b * NEWL + t] = ts[t];
        if (t <= NEWL) g_off[b * (NEWL + 1) + t] = off[t];
    } else {
        // ---- almat: (B,K,L,48) one-hot, float4 stores, 32-bit indexing ----
        unsigned g   = (blockIdx.x - Bq) * 256u + t;   // float4 index, exact cover
        unsigned row = g / 12u;              // (b,k,l) flat
        unsigned q   = g - row * 12u;
        unsigned l   = row & (Lq - 1);
        unsigned b   = row >> 15;            // / (K*L), K*L = 2^15
        float tv = __ldg(&et[b * Lq + l]);
        int s = (tv >= 0.f && tv < 48.f) ? (int)tv : NEWL;
        float4 v = make_float4(0.f, 0.f, 0.f, 0.f);
        int o = s - (int)(q * 4u);
        if (o >= 0 && o < 4) (&v.x)[o] = 1.f;
        reinterpret_cast<float4*>(out_a)[g] = v;
    }
}

// K2: segmax + pad_mask + event_time. grid = (6, B*K), block = 256 (8 warps).
// Warp w owns segment s = bx*8 + w for column bk. Main loop keeps 8 independent
// LDG.128 in flight (MLP=8) before folding into 4 accumulators.
__global__ void __launch_bounds__(256) segmax_kernel(const float* __restrict__ h0,
                                                     const float* __restrict__ npm,
                                                     float* __restrict__ o_h,
                                                     float* __restrict__ o_pm,
                                                     float* __restrict__ o_et) {
    const int bk = blockIdx.y;            // 0..511
    const int b  = bk >> 5;               // K = 32
    const int w  = threadIdx.x >> 5;      // warp 0..7
    const int j  = threadIdx.x & 31;      // lane
    const int s  = blockIdx.x * 8 + w;    // this warp's segment

    const int off = __ldg(&g_off[b * (NEWL + 1) + s]);
    const int cnt = __ldg(&g_off[b * (NEWL + 1) + s + 1]) - off;
    const int* idx = g_order + b * Lq + off;

    const float4* base4 = reinterpret_cast<const float4*>(h0 + (size_t)bk * Lq * Dq) + j;
    float4 a0 = make_float4(NEG_INF, NEG_INF, NEG_INF, NEG_INF);
    float4 a1 = a0, a2 = a0, a3 = a0;
    int i = 0;
    for (; i + 8 <= cnt; i += 8) {
        int l0 = __ldg(&idx[i]);     int l1 = __ldg(&idx[i + 1]);
        int l2 = __ldg(&idx[i + 2]); int l3 = __ldg(&idx[i + 3]);
        int l4 = __ldg(&idx[i + 4]); int l5 = __ldg(&idx[i + 5]);
        int l6 = __ldg(&idx[i + 6]); int l7 = __ldg(&idx[i + 7]);
        float4 v0 = base4[l0 * 32];
        float4 v1 = base4[l1 * 32];
        float4 v2 = base4[l2 * 32];
        float4 v3 = base4[l3 * 32];
        float4 v4 = base4[l4 * 32];
        float4 v5 = base4[l5 * 32];
        float4 v6 = base4[l6 * 32];
        float4 v7 = base4[l7 * 32];
        FMAX4(a0, v0); FMAX4(a1, v1); FMAX4(a2, v2); FMAX4(a3, v3);
        FMAX4(a0, v4); FMAX4(a1, v5); FMAX4(a2, v6); FMAX4(a3, v7);
    }
    for (; i + 4 <= cnt; i += 4) {
        int l0 = __ldg(&idx[i]);     int l1 = __ldg(&idx[i + 1]);
        int l2 = __ldg(&idx[i + 2]); int l3 = __ldg(&idx[i + 3]);
        float4 v0 = base4[l0 * 32];
        float4 v1 = base4[l1 * 32];
        float4 v2 = base4[l2 * 32];
        float4 v3 = base4[l3 * 32];
        FMAX4(a0, v0); FMAX4(a1, v1); FMAX4(a2, v2); FMAX4(a3, v3);
    }
    for (; i < cnt; ++i) {
        float4 v = base4[__ldg(&idx[i]) * 32];
        FMAX4(a0, v);
    }
    FMAX4(a0, a1); FMAX4(a2, a3); FMAX4(a0, a2);
    if (cnt < Lq) {                        // include_zero (empty segs: -inf -> 0)
        float4 z = make_float4(0.f, 0.f, 0.f, 0.f);
        FMAX4(a0, z);
    }
    reinterpret_cast<float4*>(o_h)[((size_t)bk * NEWL + s) * 32 + j] = a0;

    // msum (exact: 0/1 values), lane-strided gather + shuffle reduce
    const float* mrow = npm + (size_t)bk * Lq;
    float msum = 0.f;
    for (int i2 = j; i2 < cnt; i2 += 32) msum += mrow[__ldg(&idx[i2])];
    #pragma unroll
    for (int d = 16; d > 0; d >>= 1) msum += __shfl_down_sync(0xffffffffu, msum, d);
    if (j == 0) {
        float denom = fmaxf((float)cnt, 1.f);
        o_pm[bk * NEWL + s] = msum / denom;
        o_et[bk * NEWL + s] = __ldg(&g_tsum[b * NEWL + s]) / denom;
    }
}

extern "C" void kernel_launch(void* const* d_in, const int* in_sizes, int n_in,
                              void* d_out, int out_size) {
    const float* h0  = (const float*)d_in[0];
    const float* et  = (const float*)d_in[1];
    const float* npm = (const float*)d_in[2];
    float* out = (float*)d_out;

    float* o_h  = out;                              // (16,32,48,128) = 3,145,728
    float* o_et = out + 3145728;                    // (16,32,48)     =    24,576
    float* o_pm = out + 3145728 + 24576;            // (16,32,48)     =    24,576
    float* o_a  = out + 3145728 + 24576 + 24576;    // (16,32,1024,48)= 25,165,824

    fused_kernel<<<Bq + 24576, 256>>>(et, o_a);     // prep blocks hidden in almat
    dim3 grid(6, Bq * Kq);
    segmax_kernel<<<grid, 256>>>(h0, npm, o_h, o_pm, o_et);
}